// round 6
// baseline (speedup 1.0000x reference)
#include <cuda_runtime.h>
#include <math.h>
#include <mma.h>
using namespace nvcuda;

#define NPIX 4096
#define NTOT (4 * NPIX)

// ---------------- scratch ----------------
__device__ float g_edge32[4 * 1024 * 128];   // pixel-major [b][p32][c]
__device__ float g_fused32[4 * 1024 * 128];  // pixel-major
__device__ float g_xq[4 * 128 * NPIX];       // c-major [b][c][p]
__device__ float g_fusedT[4 * 128 * NPIX];   // c-major
__device__ float g_xk[4 * 128 * NPIX];       // sem*density, c-major
__device__ float g_v[NTOT * 256];            // [bp][c]
__device__ float g_l2e[NTOT];
__device__ float g_dens[NTOT];
__device__ float g_q[NTOT * 256];            // [bp][o]
__device__ float g_k[NTOT * 256];            // [bp][o]
__device__ float g_aoT[4 * 256 * NPIX];      // attention out, c-major [b][c][p]
__device__ float g_wqT[128 * 256];           // folded wq, [c][o]
__device__ float g_wkT[256 * 256];           // [c][o]
__device__ float g_wfT[256 * 128];           // [c][o]

__device__ __forceinline__ void cp16(void* dst, const void* src) {
    unsigned d = (unsigned)__cvta_generic_to_shared(dst);
    asm volatile("cp.async.cg.shared.global [%0], [%1], 16;" ::"r"(d), "l"(src) : "memory");
}
__device__ __forceinline__ void cp_commit() {
    asm volatile("cp.async.commit_group;" ::: "memory");
}
template <int N>
__device__ __forceinline__ void cp_wait() {
    asm volatile("cp.async.wait_group %0;" ::"n"(N) : "memory");
}

// ---------------- W prep ----------------
__global__ void wprep_kernel(const float* __restrict__ wq, const float* __restrict__ wk,
                             const float* __restrict__ wf) {
    int i = blockIdx.x * 256 + threadIdx.x;   // 131072
    if (i < 32768) {
        int c = i >> 8, o = i & 255;
        g_wqT[i] = wq[o * 256 + c] + wq[o * 256 + c + 128];
    } else if (i < 98304) {
        int j = i - 32768;
        int c = j >> 8, o = j & 255;
        g_wkT[j] = wk[o * 256 + c];
    } else {
        int j = i - 98304;
        int c = j >> 7, o = j & 127;
        g_wfT[j] = wf[o * 256 + c];
    }
}

// ---------------- K0: 1x1 convs at 32x32, pixel-major output ----------------
__global__ void conv32_kernel(const float* __restrict__ ef, const float* __restrict__ ff,
                              const float* __restrict__ wa, const float* __restrict__ ba,
                              const float* __restrict__ wfa, const float* __restrict__ bfa) {
    __shared__ float xe[64];
    __shared__ float xf[128];
    int bp = blockIdx.x;
    int b = bp >> 10, p = bp & 1023;
    int t = threadIdx.x;
    if (t < 64) xe[t] = ef[(b * 64 + t) * 1024 + p];
    xf[t] = ff[(b * 128 + t) * 1024 + p];
    __syncthreads();
    float a = ba[t];
#pragma unroll 8
    for (int ci = 0; ci < 64; ci++) a += wa[t * 64 + ci] * xe[ci];
    g_edge32[(b * 1024 + p) * 128 + t] = a;
    float a2 = bfa[t];
#pragma unroll 8
    for (int ci = 0; ci < 128; ci++) a2 += wfa[t * 128 + ci] * xf[ci];
    g_fused32[(b * 1024 + p) * 128 + t] = a2;
}

// ---------------- K1: bilinear + cosine sim + build X/V ----------------
__global__ void prep_kernel(const float* __restrict__ sem) {
    int bp = blockIdx.x;
    int b = bp >> 12, p = bp & 4095;
    int oy = p >> 6, ox = p & 63;
    int c = threadIdx.x;

    float sy = oy * 0.5f - 0.25f;
    int y0i = (int)floorf(sy);
    float wy = sy - (float)y0i;
    int y0 = y0i < 0 ? 0 : y0i;
    int y1 = (y0i + 1) > 31 ? 31 : (y0i + 1);
    float sx = ox * 0.5f - 0.25f;
    int x0i = (int)floorf(sx);
    float wx = sx - (float)x0i;
    int x0 = x0i < 0 ? 0 : x0i;
    int x1 = (x0i + 1) > 31 ? 31 : (x0i + 1);

    const float* e32 = g_edge32 + (b << 17);
    const float* f32 = g_fused32 + (b << 17);
    int i00 = (y0 * 32 + x0) << 7, i01 = (y0 * 32 + x1) << 7;
    int i10 = (y1 * 32 + x0) << 7, i11 = (y1 * 32 + x1) << 7;
    float ev = (1.f - wy) * ((1.f - wx) * e32[i00 + c] + wx * e32[i01 + c]) +
               wy * ((1.f - wx) * e32[i10 + c] + wx * e32[i11 + c]);
    float fv = (1.f - wy) * ((1.f - wx) * f32[i00 + c] + wx * f32[i01 + c]) +
               wy * ((1.f - wx) * f32[i10 + c] + wx * f32[i11 + c]);
    float sv = sem[(b * 128 + c) * 4096 + p];

    float a = ev * ev, d = ev * sv, s2 = sv * sv;
#pragma unroll
    for (int o = 16; o; o >>= 1) {
        a += __shfl_xor_sync(0xffffffffu, a, o);
        d += __shfl_xor_sync(0xffffffffu, d, o);
        s2 += __shfl_xor_sync(0xffffffffu, s2, o);
    }
    __shared__ float ra[4], rd[4], rs[4];
    int w = c >> 5;
    if ((c & 31) == 0) { ra[w] = a; rd[w] = d; rs[w] = s2; }
    __syncthreads();
    a = ra[0] + ra[1] + ra[2] + ra[3];
    d = rd[0] + rd[1] + rd[2] + rd[3];
    s2 = rs[0] + rs[1] + rs[2] + rs[3];
    float l2e = sqrtf(a), l2s = sqrtf(s2);
    float sim = (d / ((l2e + 1e-6f) * (l2s + 1e-6f)) + 1.f) * 0.5f;

    if (c == 0) g_l2e[bp] = l2e;
    g_xq[(b * 128 + c) * 4096 + p] = ev * sim;
    g_fusedT[(b * 128 + c) * 4096 + p] = fv;
    g_v[bp * 256 + c] = sv;
    g_v[bp * 256 + 128 + c] = fv;
}

// ---------------- K2: density softmax ----------------
__global__ void density_kernel() {
    __shared__ float red[32];
    __shared__ float red2[32];
    __shared__ float bmax, bsum;
    int b = blockIdx.x, t = threadIdx.x;
    float v[4];
    float mx = -1e30f;
#pragma unroll
    for (int i = 0; i < 4; i++) { v[i] = g_l2e[b * 4096 + t + i * 1024]; mx = fmaxf(mx, v[i]); }
#pragma unroll
    for (int d = 16; d; d >>= 1) mx = fmaxf(mx, __shfl_xor_sync(~0u, mx, d));
    if ((t & 31) == 0) red[t >> 5] = mx;
    __syncthreads();
    if (t < 32) {
        float m2 = red[t];
#pragma unroll
        for (int d = 16; d; d >>= 1) m2 = fmaxf(m2, __shfl_xor_sync(~0u, m2, d));
        if (t == 0) bmax = m2;
    }
    __syncthreads();
    float m = bmax;
    float s = 0.f;
#pragma unroll
    for (int i = 0; i < 4; i++) { v[i] = expf(v[i] - m); s += v[i]; }
#pragma unroll
    for (int d = 16; d; d >>= 1) s += __shfl_xor_sync(~0u, s, d);
    if ((t & 31) == 0) red2[t >> 5] = s;
    __syncthreads();
    if (t < 32) {
        float s2 = red2[t];
#pragma unroll
        for (int d = 16; d; d >>= 1) s2 += __shfl_xor_sync(~0u, s2, d);
        if (t == 0) bsum = s2;
    }
    __syncthreads();
    float f = 4096.f / bsum;
#pragma unroll
    for (int i = 0; i < 4; i++) g_dens[b * 4096 + t + i * 1024] = v[i] * f;
}

// ---------------- scale: g_xk = sem * density ----------------
__global__ void scale_kernel(const float* __restrict__ sem) {
    int i = blockIdx.x * 256 + threadIdx.x;
    int p4 = i & 1023;
    int b = i >> 17;
    float4 s = ((const float4*)sem)[i];
    float4 d = ((const float4*)(g_dens + (b << 12)))[p4];
    ((float4*)g_xk)[i] = make_float4(s.x * d.x, s.y * d.y, s.z * d.z, s.w * d.w);
}

// ---------------- TF32 tensor-core GEMM: 128px x 128o per CTA ----------------
// mode 0: Q  (K=128, OW=256, X=g_xq,          W=g_wqT, out=g_q  px-major)
// mode 1: K  (K=256, OW=256, X=g_xk|g_fusedT, W=g_wkT, out=g_k  px-major)
// mode 2: F  (K=256, OW=128, X=g_aoT,         W=g_wfT, out=outp o-major)
__global__ void gemm_tc_kernel(int mode, const float* __restrict__ bias, float* __restrict__ outp) {
    __shared__ float Xs[2][8][132];
    __shared__ float Ws[2][8][132];
    __shared__ float Bs[16][132];
    int t = threadIdx.x;
    int b = blockIdx.z;
    int px0 = blockIdx.x * 128;
    int o0 = blockIdx.y * 128;
    int kkS = t >> 5;
    int f4S = (t & 31) << 2;
    int warp = t >> 5;
    int wpx = (warp & 3) * 32;   // warp px offset (4 warps)
    int wo = (warp >> 2) * 64;   // warp o offset  (2 warps)

    int Kdim = (mode == 0) ? 128 : 256;
    int OW = (mode == 2) ? 128 : 256;
    const float* W = (mode == 0) ? g_wqT : (mode == 1 ? g_wkT : g_wfT);

    auto xrow = [&](int c) -> const float* {
        if (mode == 2) return g_aoT + (((size_t)(b << 8) + c) << 12);
        if (mode == 1 && c >= 128) return g_fusedT + (((size_t)(b << 7) + (c - 128)) << 12);
        const float* base = (mode == 0) ? g_xq : g_xk;
        return base + (((size_t)(b << 7) + c) << 12);
    };
    auto stage = [&](int k0, int buf) {
        cp16(&Xs[buf][kkS][f4S], xrow(k0 + kkS) + px0 + f4S);
        cp16(&Ws[buf][kkS][f4S], W + (k0 + kkS) * OW + o0 + f4S);
        cp_commit();
    };

    // bias tile (16 identical rows) -> accumulator init
    for (int i = t; i < 2048; i += 256) Bs[i >> 7][i & 127] = bias[o0 + (i & 127)];

    stage(0, 0);
    __syncthreads();

    wmma::fragment<wmma::accumulator, 16, 16, 8, float> acc[2][4];
#pragma unroll
    for (int i = 0; i < 2; i++)
#pragma unroll
        for (int j = 0; j < 4; j++)
            wmma::load_matrix_sync(acc[i][j], &Bs[0][wo + j * 16], 132, wmma::mem_row_major);

    int nk = Kdim >> 3;
    for (int s = 0; s < nk; s++) {
        int buf = s & 1;
        if (s + 1 < nk) { stage((s + 1) << 3, buf ^ 1); cp_wait<1>(); }
        else cp_wait<0>();
        __syncthreads();

        wmma::fragment<wmma::matrix_a, 16, 16, 8, wmma::precision::tf32, wmma::col_major> af[2];
        wmma::fragment<wmma::matrix_b, 16, 16, 8, wmma::precision::tf32, wmma::row_major> bf[4];
#pragma unroll
        for (int i = 0; i < 2; i++) {
            wmma::load_matrix_sync(af[i], &Xs[buf][0][wpx + i * 16], 132);
#pragma unroll
            for (int e = 0; e < af[i].num_elements; e++) af[i].x[e] = wmma::__float_to_tf32(af[i].x[e]);
        }
#pragma unroll
        for (int j = 0; j < 4; j++) {
            wmma::load_matrix_sync(bf[j], &Ws[buf][0][wo + j * 16], 132);
#pragma unroll
            for (int e = 0; e < bf[j].num_elements; e++) bf[j].x[e] = wmma::__float_to_tf32(bf[j].x[e]);
        }
#pragma unroll
        for (int i = 0; i < 2; i++)
#pragma unroll
            for (int j = 0; j < 4; j++)
                wmma::mma_sync(acc[i][j], af[i], bf[j], acc[i][j]);
        __syncthreads();
    }

    if (mode < 2) {
        float* out = (mode == 0) ? g_q : g_k;
#pragma unroll
        for (int i = 0; i < 2; i++)
#pragma unroll
            for (int j = 0; j < 4; j++) {
                float* p = out + (((size_t)(b << 12) + px0 + wpx + i * 16) << 8) + o0 + wo + j * 16;
                wmma::store_matrix_sync(p, acc[i][j], 256, wmma::mem_row_major);
            }
    } else {
#pragma unroll
        for (int i = 0; i < 2; i++)
#pragma unroll
            for (int j = 0; j < 4; j++) {
                float* p = outp + (((size_t)(b << 7) + o0 + wo + j * 16) << 12) + px0 + wpx + i * 16;
                wmma::store_matrix_sync(p, acc[i][j], 4096, wmma::mem_col_major);
            }
    }
}

// ---------------- K5: windowed attention (unchanged from R4) ----------------
#define KVS 68
#define ATTN_SMEM ((32 * 256 + 32 * 256 + 2 * 256 * KVS) * 4 + 2048)

__global__ void attn_kernel() {
    extern __shared__ float sm[];
    float* q_s = sm;
    float* Ssm = q_s + 32 * 256;
    float* kvb[2];
    kvb[0] = Ssm + 32 * 256;
    kvb[1] = kvb[0] + 256 * KVS;
    int* mky = (int*)(kvb[1] + 256 * KVS);
    int* mkx = mky + 256;

    int t = threadIdx.x;
    int blk = blockIdx.x;
    int b = blk >> 7;
    int tile = blk & 127;
    int qy0 = (tile >> 4) * 8, qx0 = (tile & 15) * 4;
    int uy0 = qy0 - 5 < 0 ? 0 : qy0 - 5;
    int uy1 = qy0 + 12 > 63 ? 63 : qy0 + 12;
    int ux0 = qx0 - 5 < 0 ? 0 : qx0 - 5;
    int ux1 = qx0 + 8 > 63 ? 63 : qx0 + 8;
    int uw = ux1 - ux0 + 1;
    int M = (uy1 - uy0 + 1) * uw;

    if (t < 256) {
        int ry = t / uw;
        mky[t] = uy0 + ry;
        mkx[t] = ux0 + (t - ry * uw);
    }
    __syncthreads();

    for (int i = t; i < 2048; i += 512) {
        int qi = i >> 6, f4 = (i & 63) << 2;
        int qy = qy0 + (qi >> 2), qx = qx0 + (qi & 3);
        cp16(q_s + qi * 256 + f4, g_q + ((((b << 12) + (qy << 6) + qx) << 8) + f4));
    }
    cp_commit();

    for (int i = t; i < (M << 4); i += 512) {
        int r = i >> 4, f4 = (i & 15) << 2;
        int m = (mky[r] << 6) + mkx[r];
        cp16(kvb[0] + r * KVS + f4, g_k + ((((b << 12) + m) << 8) + f4));
    }
    cp_commit();

    int qg = t >> 6, mg = t & 63;
    float acc[4][4];
#pragma unroll
    for (int u = 0; u < 4; u++)
#pragma unroll
        for (int j = 0; j < 4; j++) acc[u][j] = 0.f;

    for (int ch = 0; ch < 4; ch++) {
        {
            const float* src = (ch < 3) ? g_k : g_v;
            int nch = (ch < 3) ? ch + 1 : 0;
            float* dst = kvb[(ch + 1) & 1];
            for (int i = t; i < (M << 4); i += 512) {
                int r = i >> 4, f4 = (i & 15) << 2;
                int m = (mky[r] << 6) + mkx[r];
                cp16(dst + r * KVS + f4, src + ((((b << 12) + m) << 8) + (nch << 6) + f4));
            }
            cp_commit();
        }
        cp_wait<1>();
        __syncthreads();
        const float* kb = kvb[ch & 1];
#pragma unroll
        for (int c4 = 0; c4 < 16; c4++) {
            float4 qv[4], kvv[4];
#pragma unroll
            for (int u = 0; u < 4; u++)
                qv[u] = *(float4*)&q_s[(qg + 8 * u) * 256 + (ch << 6) + (c4 << 2)];
#pragma unroll
            for (int j = 0; j < 4; j++)
                kvv[j] = *(const float4*)&kb[(mg + 64 * j) * KVS + (c4 << 2)];
#pragma unroll
            for (int u = 0; u < 4; u++)
#pragma unroll
                for (int j = 0; j < 4; j++)
                    acc[u][j] += qv[u].x * kvv[j].x + qv[u].y * kvv[j].y +
                                 qv[u].z * kvv[j].z + qv[u].w * kvv[j].w;
        }
        __syncthreads();
    }

#pragma unroll
    for (int u = 0; u < 4; u++) {
        int qi = qg + 8 * u;
        int qy = qy0 + (qi >> 2), qx = qx0 + (qi & 3);
#pragma unroll
        for (int j = 0; j < 4; j++) {
            int s = mg + 64 * j;
            float val = -1e30f;
            if (s < M) {
                int dy = mky[s] - qy; if (dy < 0) dy = -dy;
                int dx = mkx[s] - qx; if (dx < 0) dx = -dx;
                if (dy <= 5 && dx <= 5) val = acc[u][j] * 0.0625f;
            }
            Ssm[qi * 256 + s] = val;
        }
    }
    __syncthreads();

    {
        int qi = t >> 4, l = t & 15;
        float v[16];
        float mx = -1e30f;
#pragma unroll
        for (int k = 0; k < 16; k++) { v[k] = Ssm[qi * 256 + l + 16 * k]; mx = fmaxf(mx, v[k]); }
#pragma unroll
        for (int d = 8; d; d >>= 1) mx = fmaxf(mx, __shfl_xor_sync(~0u, mx, d));
        float s = 0.f;
#pragma unroll
        for (int k = 0; k < 16; k++) { v[k] = expf(v[k] - mx); s += v[k]; }
#pragma unroll
        for (int d = 8; d; d >>= 1) s += __shfl_xor_sync(~0u, s, d);
        float inv = 1.f / s;
#pragma unroll
        for (int k = 0; k < 16; k++) Ssm[qi * 256 + l + 16 * k] = v[k] * inv;
    }

    int pair = t >> 5;
    int c2 = (t & 31) << 1;
    int q0 = pair << 1;
    int qy = qy0 + (q0 >> 2), qxA = qx0 + (q0 & 3);
    int kylo = qy - 5 < 0 ? 0 : qy - 5;
    int kyhi = qy + 5 > 63 ? 63 : qy + 5;
    int kxlo = qxA - 5 < 0 ? 0 : qxA - 5;
    int kxhi = qxA + 6 > 63 ? 63 : qxA + 6;
    int pix = (qy << 6) + qxA;

    for (int ch = 0; ch < 4; ch++) {
        if (ch < 3) {
            float* dst = kvb[(ch + 1) & 1];
            for (int i = t; i < (M << 4); i += 512) {
                int r = i >> 4, f4 = (i & 15) << 2;
                int m = (mky[r] << 6) + mkx[r];
                cp16(dst + r * KVS + f4, g_v + ((((b << 12) + m) << 8) + ((ch + 1) << 6) + f4));
            }
            cp_commit();
            cp_wait<1>();
        } else {
            cp_wait<0>();
        }
        __syncthreads();
        const float* kb = kvb[ch & 1];
        float a00 = 0.f, a01 = 0.f, a10 = 0.f, a11 = 0.f;
        for (int ky = kylo; ky <= kyhi; ky++) {
            int sb = (ky - uy0) * uw - ux0;
#pragma unroll 4
            for (int kx = kxlo; kx <= kxhi; kx++) {
                int s = sb + kx;
                float p0 = Ssm[q0 * 256 + s];
                float p1 = Ssm[q0 * 256 + 256 + s];
                float2 vv = *(const float2*)&kb[s * KVS + c2];
                a00 += p0 * vv.x; a01 += p0 * vv.y;
                a10 += p1 * vv.x; a11 += p1 * vv.y;
            }
        }
        int c = (ch << 6) + c2;
        float* base = g_aoT + (((size_t)(b << 8) + c) << 12) + pix;
        base[0] = a00;
        base[4096] = a01;
        base[1] = a10;
        base[4097] = a11;
        __syncthreads();
    }
}

// ---------------- launch ----------------
extern "C" void kernel_launch(void* const* d_in, const int* in_sizes, int n_in,
                              void* d_out, int out_size) {
    const float* ef  = (const float*)d_in[0];
    const float* sem = (const float*)d_in[1];
    const float* ff  = (const float*)d_in[2];
    const float* wa  = (const float*)d_in[3];
    const float* ba  = (const float*)d_in[4];
    const float* wfa = (const float*)d_in[5];
    const float* bfa = (const float*)d_in[6];
    const float* wq  = (const float*)d_in[7];
    const float* bq  = (const float*)d_in[8];
    const float* wk  = (const float*)d_in[9];
    const float* bk  = (const float*)d_in[10];
    const float* wfu = (const float*)d_in[11];
    const float* bfu = (const float*)d_in[12];
    float* out = (float*)d_out;

    wprep_kernel<<<512, 256>>>(wq, wk, wfu);
    conv32_kernel<<<4096, 128>>>(ef, ff, wa, ba, wfa, bfa);
    prep_kernel<<<16384, 128>>>(sem);
    density_kernel<<<4, 1024>>>();
    scale_kernel<<<2048, 256>>>(sem);
    gemm_tc_kernel<<<dim3(32, 2, 4), 256>>>(0, bq, nullptr);
    gemm_tc_kernel<<<dim3(32, 2, 4), 256>>>(1, bk, nullptr);
    cudaFuncSetAttribute(attn_kernel, cudaFuncAttributeMaxDynamicSharedMemorySize, ATTN_SMEM);
    attn_kernel<<<512, 512, ATTN_SMEM>>>();
    gemm_tc_kernel<<<dim3(32, 1, 4), 256>>>(2, bfu, out);
}

// round 7
// speedup vs baseline: 1.0301x; 1.0301x over previous
#include <cuda_runtime.h>
#include <math.h>
#include <mma.h>
using namespace nvcuda;

#define NPIX 4096
#define NTOT (4 * NPIX)

// ---------------- scratch ----------------
__device__ float g_edge32[4 * 1024 * 128];   // pixel-major [b][p32][c]
__device__ float g_fused32[4 * 1024 * 128];  // pixel-major
__device__ float g_xq[4 * 128 * NPIX];       // c-major [b][c][p]
__device__ float g_fusedT[4 * 128 * NPIX];   // c-major
__device__ float g_xk[4 * 128 * NPIX];       // sem*density, c-major
__device__ float g_v[NTOT * 256];            // [bp][c]
__device__ float g_l2e[NTOT];
__device__ float g_dens[NTOT];
__device__ float g_q[NTOT * 256];            // [bp][o]
__device__ float g_k[NTOT * 256];            // [bp][o]
__device__ float g_aoT[4 * 256 * NPIX];      // attention out, c-major [b][c][p]
__device__ float g_wqT[128 * 256];           // folded wq, [c][o]
__device__ float g_wkT[256 * 256];           // [c][o]
__device__ float g_wfT[256 * 128];           // [c][o]

__device__ __forceinline__ void cp16(void* dst, const void* src) {
    unsigned d = (unsigned)__cvta_generic_to_shared(dst);
    asm volatile("cp.async.cg.shared.global [%0], [%1], 16;" ::"r"(d), "l"(src) : "memory");
}
__device__ __forceinline__ void cp_commit() {
    asm volatile("cp.async.commit_group;" ::: "memory");
}
template <int N>
__device__ __forceinline__ void cp_wait() {
    asm volatile("cp.async.wait_group %0;" ::"n"(N) : "memory");
}

// ---------------- K0: conv1x1 @32x32 (blocks 0..4095) + weight prep (blocks 4096..5119) ----
__global__ void conv32w_kernel(const float* __restrict__ ef, const float* __restrict__ ff,
                               const float* __restrict__ wa, const float* __restrict__ ba,
                               const float* __restrict__ wfa, const float* __restrict__ bfa,
                               const float* __restrict__ wq, const float* __restrict__ wk,
                               const float* __restrict__ wf) {
    int t = threadIdx.x;
    if (blockIdx.x >= 4096) {
        int i = (blockIdx.x - 4096) * 128 + t;   // 131072 total
        if (i < 32768) {
            int c = i >> 8, o = i & 255;
            g_wqT[i] = wq[o * 256 + c] + wq[o * 256 + c + 128];
        } else if (i < 98304) {
            int j = i - 32768;
            int c = j >> 8, o = j & 255;
            g_wkT[j] = wk[o * 256 + c];
        } else {
            int j = i - 98304;
            int c = j >> 7, o = j & 127;
            g_wfT[j] = wf[o * 256 + c];
        }
        return;
    }
    __shared__ float xe[64];
    __shared__ float xf[128];
    int bp = blockIdx.x;
    int b = bp >> 10, p = bp & 1023;
    if (t < 64) xe[t] = ef[(b * 64 + t) * 1024 + p];
    xf[t] = ff[(b * 128 + t) * 1024 + p];
    __syncthreads();
    float a = ba[t];
#pragma unroll 8
    for (int ci = 0; ci < 64; ci++) a += wa[t * 64 + ci] * xe[ci];
    g_edge32[(b * 1024 + p) * 128 + t] = a;
    float a2 = bfa[t];
#pragma unroll 8
    for (int ci = 0; ci < 128; ci++) a2 += wfa[t * 128 + ci] * xf[ci];
    g_fused32[(b * 1024 + p) * 128 + t] = a2;
}

// ---------------- K1: bilinear + cosine sim + build X/V ----------------
__global__ void prep_kernel(const float* __restrict__ sem) {
    int bp = blockIdx.x;
    int b = bp >> 12, p = bp & 4095;
    int oy = p >> 6, ox = p & 63;
    int c = threadIdx.x;

    float sy = oy * 0.5f - 0.25f;
    int y0i = (int)floorf(sy);
    float wy = sy - (float)y0i;
    int y0 = y0i < 0 ? 0 : y0i;
    int y1 = (y0i + 1) > 31 ? 31 : (y0i + 1);
    float sx = ox * 0.5f - 0.25f;
    int x0i = (int)floorf(sx);
    float wx = sx - (float)x0i;
    int x0 = x0i < 0 ? 0 : x0i;
    int x1 = (x0i + 1) > 31 ? 31 : (x0i + 1);

    const float* e32 = g_edge32 + (b << 17);
    const float* f32 = g_fused32 + (b << 17);
    int i00 = (y0 * 32 + x0) << 7, i01 = (y0 * 32 + x1) << 7;
    int i10 = (y1 * 32 + x0) << 7, i11 = (y1 * 32 + x1) << 7;
    float ev = (1.f - wy) * ((1.f - wx) * e32[i00 + c] + wx * e32[i01 + c]) +
               wy * ((1.f - wx) * e32[i10 + c] + wx * e32[i11 + c]);
    float fv = (1.f - wy) * ((1.f - wx) * f32[i00 + c] + wx * f32[i01 + c]) +
               wy * ((1.f - wx) * f32[i10 + c] + wx * f32[i11 + c]);
    float sv = sem[(b * 128 + c) * 4096 + p];

    float a = ev * ev, d = ev * sv, s2 = sv * sv;
#pragma unroll
    for (int o = 16; o; o >>= 1) {
        a += __shfl_xor_sync(0xffffffffu, a, o);
        d += __shfl_xor_sync(0xffffffffu, d, o);
        s2 += __shfl_xor_sync(0xffffffffu, s2, o);
    }
    __shared__ float ra[4], rd[4], rs[4];
    int w = c >> 5;
    if ((c & 31) == 0) { ra[w] = a; rd[w] = d; rs[w] = s2; }
    __syncthreads();
    a = ra[0] + ra[1] + ra[2] + ra[3];
    d = rd[0] + rd[1] + rd[2] + rd[3];
    s2 = rs[0] + rs[1] + rs[2] + rs[3];
    float l2e = sqrtf(a), l2s = sqrtf(s2);
    float sim = (d / ((l2e + 1e-6f) * (l2s + 1e-6f)) + 1.f) * 0.5f;

    if (c == 0) g_l2e[bp] = l2e;
    g_xq[(b * 128 + c) * 4096 + p] = ev * sim;
    g_fusedT[(b * 128 + c) * 4096 + p] = fv;
    g_v[bp * 256 + c] = sv;
    g_v[bp * 256 + 128 + c] = fv;
}

// ---------------- K2: density softmax ----------------
__global__ void density_kernel() {
    __shared__ float red[32];
    __shared__ float red2[32];
    __shared__ float bmax, bsum;
    int b = blockIdx.x, t = threadIdx.x;
    float v[4];
    float mx = -1e30f;
#pragma unroll
    for (int i = 0; i < 4; i++) { v[i] = g_l2e[b * 4096 + t + i * 1024]; mx = fmaxf(mx, v[i]); }
#pragma unroll
    for (int d = 16; d; d >>= 1) mx = fmaxf(mx, __shfl_xor_sync(~0u, mx, d));
    if ((t & 31) == 0) red[t >> 5] = mx;
    __syncthreads();
    if (t < 32) {
        float m2 = red[t];
#pragma unroll
        for (int d = 16; d; d >>= 1) m2 = fmaxf(m2, __shfl_xor_sync(~0u, m2, d));
        if (t == 0) bmax = m2;
    }
    __syncthreads();
    float m = bmax;
    float s = 0.f;
#pragma unroll
    for (int i = 0; i < 4; i++) { v[i] = expf(v[i] - m); s += v[i]; }
#pragma unroll
    for (int d = 16; d; d >>= 1) s += __shfl_xor_sync(~0u, s, d);
    if ((t & 31) == 0) red2[t >> 5] = s;
    __syncthreads();
    if (t < 32) {
        float s2 = red2[t];
#pragma unroll
        for (int d = 16; d; d >>= 1) s2 += __shfl_xor_sync(~0u, s2, d);
        if (t == 0) bsum = s2;
    }
    __syncthreads();
    float f = 4096.f / bsum;
#pragma unroll
    for (int i = 0; i < 4; i++) g_dens[b * 4096 + t + i * 1024] = v[i] * f;
}

// ---------------- scale: g_xk = sem * density ----------------
__global__ void scale_kernel(const float* __restrict__ sem) {
    int i = blockIdx.x * 256 + threadIdx.x;
    int p4 = i & 1023;
    int b = i >> 17;
    float4 s = ((const float4*)sem)[i];
    float4 d = ((const float4*)(g_dens + (b << 12)))[p4];
    ((float4*)g_xk)[i] = make_float4(s.x * d.x, s.y * d.y, s.z * d.z, s.w * d.w);
}

// ---------------- TF32 tensor-core GEMM: 128px x 128o per CTA ----------------
__global__ void gemm_tc_kernel(int mode, const float* __restrict__ bias, float* __restrict__ outp) {
    __shared__ float Xs[2][8][132];
    __shared__ float Ws[2][8][132];
    __shared__ float Bs[16][132];
    int t = threadIdx.x;
    int b = blockIdx.z;
    int px0 = blockIdx.x * 128;
    int o0 = blockIdx.y * 128;
    int kkS = t >> 5;
    int f4S = (t & 31) << 2;
    int warp = t >> 5;
    int wpx = (warp & 3) * 32;
    int wo = (warp >> 2) * 64;

    int Kdim = (mode == 0) ? 128 : 256;
    int OW = (mode == 2) ? 128 : 256;
    const float* W = (mode == 0) ? g_wqT : (mode == 1 ? g_wkT : g_wfT);

    auto xrow = [&](int c) -> const float* {
        if (mode == 2) return g_aoT + (((size_t)(b << 8) + c) << 12);
        if (mode == 1 && c >= 128) return g_fusedT + (((size_t)(b << 7) + (c - 128)) << 12);
        const float* base = (mode == 0) ? g_xq : g_xk;
        return base + (((size_t)(b << 7) + c) << 12);
    };
    auto stage = [&](int k0, int buf) {
        cp16(&Xs[buf][kkS][f4S], xrow(k0 + kkS) + px0 + f4S);
        cp16(&Ws[buf][kkS][f4S], W + (k0 + kkS) * OW + o0 + f4S);
        cp_commit();
    };

    for (int i = t; i < 2048; i += 256) Bs[i >> 7][i & 127] = bias[o0 + (i & 127)];

    stage(0, 0);
    __syncthreads();

    wmma::fragment<wmma::accumulator, 16, 16, 8, float> acc[2][4];
#pragma unroll
    for (int i = 0; i < 2; i++)
#pragma unroll
        for (int j = 0; j < 4; j++)
            wmma::load_matrix_sync(acc[i][j], &Bs[0][wo + j * 16], 132, wmma::mem_row_major);

    int nk = Kdim >> 3;
    for (int s = 0; s < nk; s++) {
        int buf = s & 1;
        if (s + 1 < nk) { stage((s + 1) << 3, buf ^ 1); cp_wait<1>(); }
        else cp_wait<0>();
        __syncthreads();

        wmma::fragment<wmma::matrix_a, 16, 16, 8, wmma::precision::tf32, wmma::col_major> af[2];
        wmma::fragment<wmma::matrix_b, 16, 16, 8, wmma::precision::tf32, wmma::row_major> bf[4];
#pragma unroll
        for (int i = 0; i < 2; i++) {
            wmma::load_matrix_sync(af[i], &Xs[buf][0][wpx + i * 16], 132);
#pragma unroll
            for (int e = 0; e < af[i].num_elements; e++) af[i].x[e] = wmma::__float_to_tf32(af[i].x[e]);
        }
#pragma unroll
        for (int j = 0; j < 4; j++) {
            wmma::load_matrix_sync(bf[j], &Ws[buf][0][wo + j * 16], 132);
#pragma unroll
            for (int e = 0; e < bf[j].num_elements; e++) bf[j].x[e] = wmma::__float_to_tf32(bf[j].x[e]);
        }
#pragma unroll
        for (int i = 0; i < 2; i++)
#pragma unroll
            for (int j = 0; j < 4; j++)
                wmma::mma_sync(acc[i][j], af[i], bf[j], acc[i][j]);
        __syncthreads();
    }

    if (mode < 2) {
        float* out = (mode == 0) ? g_q : g_k;
#pragma unroll
        for (int i = 0; i < 2; i++)
#pragma unroll
            for (int j = 0; j < 4; j++) {
                float* p = out + (((size_t)(b << 12) + px0 + wpx + i * 16) << 8) + o0 + wo + j * 16;
                wmma::store_matrix_sync(p, acc[i][j], 256, wmma::mem_row_major);
            }
    } else {
#pragma unroll
        for (int i = 0; i < 2; i++)
#pragma unroll
            for (int j = 0; j < 4; j++) {
                float* p = outp + (((size_t)(b << 7) + o0 + wo + j * 16) << 12) + px0 + wpx + i * 16;
                wmma::store_matrix_sync(p, acc[i][j], 4096, wmma::mem_col_major);
            }
    }
}

// ---------------- K5: windowed attention — 102KB smem => 2 CTAs/SM ----------------
// smem: qS[32*256] (aliased by Ssm after QK) | kv[256*68] single buffer | mky/mkx
#define KVS 68
#define ATTN_SMEM ((32 * 256 + 256 * KVS) * 4 + 2048)

__global__ void __launch_bounds__(512, 2) attn_kernel() {
    extern __shared__ float sm[];
    float* q_s = sm;                 // 32x256, dead after QK
    float* Ssm = sm;                 // alias: scores live after QK
    float* kv = sm + 32 * 256;       // 256 x KVS
    int* mky = (int*)(kv + 256 * KVS);
    int* mkx = mky + 256;

    int t = threadIdx.x;
    int blk = blockIdx.x;
    int b = blk >> 7;
    int tile = blk & 127;
    int qy0 = (tile >> 4) * 8, qx0 = (tile & 15) * 4;
    int uy0 = qy0 - 5 < 0 ? 0 : qy0 - 5;
    int uy1 = qy0 + 12 > 63 ? 63 : qy0 + 12;
    int ux0 = qx0 - 5 < 0 ? 0 : qx0 - 5;
    int ux1 = qx0 + 8 > 63 ? 63 : qx0 + 8;
    int uw = ux1 - ux0 + 1;
    int M = (uy1 - uy0 + 1) * uw;

    if (t < 256) {
        int ry = t / uw;
        mky[t] = uy0 + ry;
        mkx[t] = ux0 + (t - ry * uw);
    }
    __syncthreads();

    // stage Q (persists through all QK chunks)
    for (int i = t; i < 2048; i += 512) {
        int qi = i >> 6, f4 = (i & 63) << 2;
        int qy = qy0 + (qi >> 2), qx = qx0 + (qi & 3);
        cp16(q_s + qi * 256 + f4, g_q + ((((b << 12) + (qy << 6) + qx) << 8) + f4));
    }
    cp_commit();

    int qg = t >> 6, mg = t & 63;
    float acc[4][4];
#pragma unroll
    for (int u = 0; u < 4; u++)
#pragma unroll
        for (int j = 0; j < 4; j++) acc[u][j] = 0.f;

    // QK: 4 chunks of 64 channels, single kv buffer
    for (int ch = 0; ch < 4; ch++) {
        for (int i = t; i < (M << 4); i += 512) {
            int r = i >> 4, f4 = (i & 15) << 2;
            int m = (mky[r] << 6) + mkx[r];
            cp16(kv + r * KVS + f4, g_k + ((((b << 12) + m) << 8) + (ch << 6) + f4));
        }
        cp_commit();
        cp_wait<0>();
        __syncthreads();
#pragma unroll
        for (int c4 = 0; c4 < 16; c4++) {
            float4 qv[4], kvv[4];
#pragma unroll
            for (int u = 0; u < 4; u++)
                qv[u] = *(float4*)&q_s[(qg + 8 * u) * 256 + (ch << 6) + (c4 << 2)];
#pragma unroll
            for (int j = 0; j < 4; j++)
                kvv[j] = *(const float4*)&kv[(mg + 64 * j) * KVS + (c4 << 2)];
#pragma unroll
            for (int u = 0; u < 4; u++)
#pragma unroll
                for (int j = 0; j < 4; j++)
                    acc[u][j] += qv[u].x * kvv[j].x + qv[u].y * kvv[j].y +
                                 qv[u].z * kvv[j].z + qv[u].w * kvv[j].w;
        }
        __syncthreads();
    }

    // scores + window mask (q_s now dead; Ssm aliases it)
#pragma unroll
    for (int u = 0; u < 4; u++) {
        int qi = qg + 8 * u;
        int qy = qy0 + (qi >> 2), qx = qx0 + (qi & 3);
#pragma unroll
        for (int j = 0; j < 4; j++) {
            int s = mg + 64 * j;
            float val = -1e30f;
            if (s < M) {
                int dy = mky[s] - qy; if (dy < 0) dy = -dy;
                int dx = mkx[s] - qx; if (dx < 0) dx = -dx;
                if (dy <= 5 && dx <= 5) val = acc[u][j] * 0.0625f;
            }
            Ssm[qi * 256 + s] = val;
        }
    }
    __syncthreads();

    // softmax (invalid slots -> exactly 0)
    {
        int qi = t >> 4, l = t & 15;
        float v[16];
        float mx = -1e30f;
#pragma unroll
        for (int k = 0; k < 16; k++) { v[k] = Ssm[qi * 256 + l + 16 * k]; mx = fmaxf(mx, v[k]); }
#pragma unroll
        for (int d = 8; d; d >>= 1) mx = fmaxf(mx, __shfl_xor_sync(~0u, mx, d));
        float s = 0.f;
#pragma unroll
        for (int k = 0; k < 16; k++) { v[k] = expf(v[k] - mx); s += v[k]; }
#pragma unroll
        for (int d = 8; d; d >>= 1) s += __shfl_xor_sync(~0u, s, d);
        float inv = 1.f / s;
#pragma unroll
        for (int k = 0; k < 16; k++) Ssm[qi * 256 + l + 16 * k] = v[k] * inv;
    }
    __syncthreads();

    // AV: thread owns query pair (same row) x float2 channels; 4 chunks, single buffer
    int pair = t >> 5;
    int c2 = (t & 31) << 1;
    int q0 = pair << 1;
    int qy = qy0 + (q0 >> 2), qxA = qx0 + (q0 & 3);
    int kylo = qy - 5 < 0 ? 0 : qy - 5;
    int kyhi = qy + 5 > 63 ? 63 : qy + 5;
    int kxlo = qxA - 5 < 0 ? 0 : qxA - 5;
    int kxhi = qxA + 6 > 63 ? 63 : qxA + 6;
    int pix = (qy << 6) + qxA;

    for (int ch = 0; ch < 4; ch++) {
        for (int i = t; i < (M << 4); i += 512) {
            int r = i >> 4, f4 = (i & 15) << 2;
            int m = (mky[r] << 6) + mkx[r];
            cp16(kv + r * KVS + f4, g_v + ((((b << 12) + m) << 8) + (ch << 6) + f4));
        }
        cp_commit();
        cp_wait<0>();
        __syncthreads();

        float a00 = 0.f, a01 = 0.f, a10 = 0.f, a11 = 0.f;
        for (int ky = kylo; ky <= kyhi; ky++) {
            int sb = (ky - uy0) * uw - ux0;
#pragma unroll 4
            for (int kx = kxlo; kx <= kxhi; kx++) {
                int s = sb + kx;
                float p0 = Ssm[q0 * 256 + s];
                float p1 = Ssm[q0 * 256 + 256 + s];
                float2 vv = *(const float2*)&kv[s * KVS + c2];
                a00 += p0 * vv.x; a01 += p0 * vv.y;
                a10 += p1 * vv.x; a11 += p1 * vv.y;
            }
        }
        int c = (ch << 6) + c2;
        float* base = g_aoT + (((size_t)(b << 8) + c) << 12) + pix;
        base[0] = a00;
        base[4096] = a01;
        base[1] = a10;
        base[4097] = a11;
        __syncthreads();
    }
}

// ---------------- launch: gemm_tc(Q) is launch index 3 (ncu captures #3) ----------------
extern "C" void kernel_launch(void* const* d_in, const int* in_sizes, int n_in,
                              void* d_out, int out_size) {
    const float* ef  = (const float*)d_in[0];
    const float* sem = (const float*)d_in[1];
    const float* ff  = (const float*)d_in[2];
    const float* wa  = (const float*)d_in[3];
    const float* ba  = (const float*)d_in[4];
    const float* wfa = (const float*)d_in[5];
    const float* bfa = (const float*)d_in[6];
    const float* wq  = (const float*)d_in[7];
    const float* bq  = (const float*)d_in[8];
    const float* wk  = (const float*)d_in[9];
    const float* bk  = (const float*)d_in[10];
    const float* wfu = (const float*)d_in[11];
    const float* bfu = (const float*)d_in[12];
    float* out = (float*)d_out;

    conv32w_kernel<<<5120, 128>>>(ef, ff, wa, ba, wfa, bfa, wq, wk, wfu);   // 0
    prep_kernel<<<16384, 128>>>(sem);                                       // 1
    density_kernel<<<4, 1024>>>();                                          // 2
    gemm_tc_kernel<<<dim3(32, 2, 4), 256>>>(0, bq, nullptr);                // 3 <- profiled
    scale_kernel<<<2048, 256>>>(sem);                                       // 4
    gemm_tc_kernel<<<dim3(32, 2, 4), 256>>>(1, bk, nullptr);                // 5
    cudaFuncSetAttribute(attn_kernel, cudaFuncAttributeMaxDynamicSharedMemorySize, ATTN_SMEM);
    attn_kernel<<<512, 512, ATTN_SMEM>>>();                                 // 6
    gemm_tc_kernel<<<dim3(32, 1, 4), 256>>>(2, bfu, out);                   // 7
}